// round 7
// baseline (speedup 1.0000x reference)
#include <cuda_runtime.h>
#include <cstdint>

#define BN 64
#define BD 512
#define BB 16

// ---------------------------------------------------------------------------
// Compile-time structure table.
// Entry = i1 | (i2<<10) | 0x40000000 for masked (i,j): content = max(L[i1],L[i2])
// over a 7-level sparse max table; -1 for unmasked.
// ---------------------------------------------------------------------------
struct TblT { int v[4096]; };

constexpr int ilog2c(int v) { int l = 0; while ((1 << (l + 1)) <= v) l++; return l; }

constexpr int pack_entry_c(int a, int b) {
    int len = b - a;
    int l = ilog2c(len);
    const int off[7] = {0, 64, 127, 188, 245, 294, 327};
    int i1 = off[l] + a;
    int i2 = off[l] + b - (1 << l);
    return i1 | (i2 << 10) | 0x40000000;
}

constexpr TblT make_tbl() {
    TblT t{};
    for (int i = 0; i < 4096; i++) t.v[i] = -1;
    int lo[64] = {}, hi[64] = {};
    for (int p = 0; p < 64; p++) {
        lo[p] = p; hi[p] = p + 1;
        t.v[p * 64 + p] = pack_entry_c(p, p + 1);
    }
    int len = 64, stride = 1, offset = 0;
    const int counts[3] = {15, 8, 8};
    for (int ci = 0; ci < 3; ci++) {
        for (int tt = 0; tt < counts[ci]; tt++) {
            offset += stride;
            int k = (ci == 0 || tt > 0) ? 2 : 3;
            int s = (k == 2) ? 1 : 2;
            int nl = (len - k) / s + 1;
            for (int p = 0; p < nl; p++) {
                int a = lo[p * s];
                int b = hi[p * s + k - 1];
                lo[p] = a; hi[p] = b;
                int i = p * stride, j = i + offset;
                t.v[i * 64 + j] = pack_entry_c(a, b);
            }
            len = nl;
        }
        stride *= 2;
    }
    return t;
}

constexpr TblT HOST_TBL = make_tbl();
__device__ const TblT g_tbl = HOST_TBL;

// Compile-time quad partition: a quad (4 consecutive cols) is all-zero iff all
// 4 table entries are -1. Zero quads are written by the fused kernel (overlapped
// with the GEMM); non-zero quads by the main kernel.
struct QL { int zq[1024]; int nq[1024]; int nz; int nn; };
constexpr QL make_ql() {
    QL r{};
    for (int q = 0; q < 1024; q++) {
        bool az = HOST_TBL.v[4 * q] < 0 && HOST_TBL.v[4 * q + 1] < 0 &&
                  HOST_TBL.v[4 * q + 2] < 0 && HOST_TBL.v[4 * q + 3] < 0;
        if (az) r.zq[r.nz++] = q; else r.nq[r.nn++] = q;
    }
    return r;
}
constexpr QL HOST_QL = make_ql();
constexpr int NZQ = HOST_QL.nz;
constexpr int NNQ = HOST_QL.nn;
__device__ const QL g_ql = HOST_QL;

struct MaskT { float v[4096]; };
constexpr MaskT make_mask() {
    MaskT m{};
    for (int i = 0; i < 4096; i++) m.v[i] = (HOST_TBL.v[i] >= 0) ? 1.f : 0.f;
    return m;
}
constexpr MaskT HOST_MASK = make_mask();
__device__ const MaskT g_mask = HOST_MASK;

// Scratch (static device globals — no allocations)
__device__ float d_part[2 * BB * 64 * 1024];  // K-split partial sums (no bias)
__device__ float d_factor[BB * 4096];         // 1 + softmax weights

// Elements per output map, and float4 stride between maps.
#define MAPSZ   ((size_t)BB * BD * 4096)
#define MAP4    (MAPSZ / 4)

// ---------------------------------------------------------------------------
// Fused kernel: 768 CTAs. bx%3!=2 -> GEMM CTA (512 of them: 16 o-tiles x 16 b
// x 2 ksplit); bx%3==2 -> zero-fill CTA (256): streams zeros into the all-zero
// quads of all three maps (+ mask plane). Interleaving keeps zero CTAs resident
// in wave 1 so the DRAM work hides under the smem/FMA-bound GEMM.
// ---------------------------------------------------------------------------
__global__ __launch_bounds__(256) void fused_kernel(
    const float* __restrict__ x, const float* __restrict__ w_v,
    const float* __restrict__ w_c, float* __restrict__ out)
{
    int bx = blockIdx.x;
    int tid = threadIdx.x;

    if (bx % 3 == 2) {
        // ------------------ zero-fill path ------------------
        int z = bx / 3;                   // 0..255, covers 32 (b,d) rows
        float4 z4 = make_float4(0.f, 0.f, 0.f, 0.f);
        float4* base0 = (float4*)out + (size_t)z * 32 * 1024;
        for (int idx = tid; idx < NZQ; idx += 256) {
            int q = g_ql.zq[idx];
            float4* p = base0 + q;
#pragma unroll 4
            for (int rr = 0; rr < 32; rr++) {
                __stcs(p, z4);
                __stcs(p + MAP4, z4);
                __stcs(p + 2 * MAP4, z4);
                p += 1024;
            }
        }
        if (z < BB) {
            const float4* mq = (const float4*)g_mask.v;
            float4* mb = (float4*)(out + 3 * MAPSZ) + (size_t)z * 1024;
            for (int idx = tid; idx < 1024; idx += 256)
                __stcs(mb + idx, mq[idx]);
        }
        return;
    }

    // ------------------ GEMM path ------------------
    int g  = bx - bx / 3;                 // 0..511
    int o0 = (g & 15) * 64;
    int b  = (g >> 4) & 15;
    int ks = g >> 8;
    const float* W = (o0 < 512) ? (w_v + (size_t)o0 * 512)
                                : (w_c + (size_t)(o0 - 512) * 512);
    W += ks * 256;
    const float* xb = x + (size_t)b * BD * BN + (size_t)ks * 256 * 64;

    __shared__ float As[2][16][64];
    __shared__ float Ws[2][16][68];

    int tx = tid & 15, ty = tid >> 4;
    float acc[4][4];
#pragma unroll
    for (int r = 0; r < 4; r++)
#pragma unroll
        for (int c = 0; c < 4; c++) acc[r][c] = 0.f;

    {
#pragma unroll
        for (int it = 0; it < 4; it++) {
            int e = tid + it * 256;
            int dd = e >> 6, n = e & 63;
            As[0][dd][n] = xb[(size_t)dd * 64 + n];
        }
        int o = tid >> 2, c4 = tid & 3;
        float4 v = *(const float4*)(W + (size_t)o * 512 + c4 * 4);
        Ws[0][c4 * 4 + 0][o] = v.x; Ws[0][c4 * 4 + 1][o] = v.y;
        Ws[0][c4 * 4 + 2][o] = v.z; Ws[0][c4 * 4 + 3][o] = v.w;
    }
    __syncthreads();

    for (int t = 0; t < 16; t++) {
        int s = t & 1, ns = s ^ 1;
        if (t < 15) {
            int kb = (t + 1) * 16;
#pragma unroll
            for (int it = 0; it < 4; it++) {
                int e = tid + it * 256;
                int dd = e >> 6, n = e & 63;
                As[ns][dd][n] = xb[(size_t)(kb + dd) * 64 + n];
            }
            int o = tid >> 2, c4 = tid & 3;
            float4 v = *(const float4*)(W + (size_t)o * 512 + kb + c4 * 4);
            Ws[ns][c4 * 4 + 0][o] = v.x; Ws[ns][c4 * 4 + 1][o] = v.y;
            Ws[ns][c4 * 4 + 2][o] = v.z; Ws[ns][c4 * 4 + 3][o] = v.w;
        }
#pragma unroll
        for (int kk = 0; kk < 16; kk++) {
            float4 a4 = *(const float4*)&As[s][kk][ty * 4];
            float4 b4 = *(const float4*)&Ws[s][kk][tx * 4];
            float av[4] = {a4.x, a4.y, a4.z, a4.w};
            float bw[4] = {b4.x, b4.y, b4.z, b4.w};
#pragma unroll
            for (int r = 0; r < 4; r++)
#pragma unroll
                for (int c = 0; c < 4; c++)
                    acc[r][c] += av[r] * bw[c];
        }
        __syncthreads();
    }

    float* dst = d_part + ((size_t)ks * BB + b) * 65536;
#pragma unroll
    for (int r = 0; r < 4; r++) {
        float4 o4 = make_float4(acc[r][0], acc[r][1], acc[r][2], acc[r][3]);
        *(float4*)&dst[(size_t)(ty * 4 + r) * 1024 + o0 + tx * 4] = o4;
    }
}

// ---------------------------------------------------------------------------
// Kernel 2: combine partials + bias on the fly; m2m = m_k @ m_q^T / 8,
// row softmax, factor = 1 + w.
// ---------------------------------------------------------------------------
__global__ __launch_bounds__(256) void attn_kernel(
    const float* __restrict__ b_v, const float* __restrict__ b_c)
{
    int b = blockIdx.y;
    int n0 = blockIdx.x * 16;
    __shared__ float Sk[16][33];
    __shared__ float Sq[32][68];
    __shared__ float sm[16][68];
    __shared__ float red[16];
    int tid = threadIdx.x;
    int tr = tid >> 4, tc = tid & 15;
    float acc[4] = {0, 0, 0, 0};
    const float* P0 = d_part + (size_t)b * 65536;
    const float* P1 = d_part + (size_t)(BB + b) * 65536;

    for (int kt = 0; kt < 512; kt += 32) {
#pragma unroll
        for (int it = 0; it < 2; it++) {
            int u = tid + it * 256;
            int r = u >> 5, kk = u & 31;
            size_t off = (size_t)(n0 + r) * 1024 + kt + kk;
            Sk[r][kk] = P0[off] + P1[off] + b_v[kt + kk];
        }
#pragma unroll
        for (int it = 0; it < 2; it++) {
            int u = tid + it * 256;
            int m = u >> 3, c4 = u & 7;
            size_t off = (size_t)m * 1024 + 512 + kt + c4 * 4;
            float4 v0 = *(const float4*)(P0 + off);
            float4 v1 = *(const float4*)(P1 + off);
            float4 vb = *(const float4*)(b_c + kt + c4 * 4);
            Sq[c4 * 4 + 0][m] = v0.x + v1.x + vb.x;
            Sq[c4 * 4 + 1][m] = v0.y + v1.y + vb.y;
            Sq[c4 * 4 + 2][m] = v0.z + v1.z + vb.z;
            Sq[c4 * 4 + 3][m] = v0.w + v1.w + vb.w;
        }
        __syncthreads();
#pragma unroll
        for (int kk = 0; kk < 32; kk++) {
            float a = Sk[tr][kk];
            float4 b4 = *(const float4*)&Sq[kk][tc * 4];
            acc[0] += a * b4.x; acc[1] += a * b4.y;
            acc[2] += a * b4.z; acc[3] += a * b4.w;
        }
        __syncthreads();
    }
#pragma unroll
    for (int c = 0; c < 4; c++) sm[tr][tc * 4 + c] = acc[c] * 0.125f;
    __syncthreads();
    if (tid < 16) {
        float mx = -1e30f;
        for (int m = 0; m < 64; m++) mx = fmaxf(mx, sm[tid][m]);
        red[tid] = mx;
    }
    __syncthreads();
    float mx = red[tr];
    float e[4];
#pragma unroll
    for (int c = 0; c < 4; c++) {
        e[c] = __expf(sm[tr][tc * 4 + c] - mx);
        sm[tr][tc * 4 + c] = e[c];
    }
    __syncthreads();
    if (tid < 16) {
        float s = 0.f;
        for (int m = 0; m < 64; m++) s += sm[tid][m];
        red[tid] = 1.f / s;
    }
    __syncthreads();
    float inv = red[tr];
#pragma unroll
    for (int c = 0; c < 4; c++)
        d_factor[(size_t)b * 4096 + (size_t)(n0 + tr) * 64 + tc * 4 + c] = 1.f + e[c] * inv;
}

// ---------------------------------------------------------------------------
// Kernel 3: masked-quad writer. One block per (b, 4 d-rows); iterates only the
// NNQ non-zero quads (compile-time list). Small smem -> high occupancy, high
// store-MLP. Streams stores with __stcs.
// ---------------------------------------------------------------------------
__global__ __launch_bounds__(256) void main_kernel(
    const float* __restrict__ x, float* __restrict__ out)
{
    __shared__ float lev[4][352];

    int b  = blockIdx.y;
    int d0 = blockIdx.x * 4;
    int tid = threadIdx.x;

    // Load 4 x-rows and build the 7-level sparse max tables in parallel.
    {
        int dg = tid >> 6, n = tid & 63;
        lev[dg][n] = x[((size_t)(b * BD + d0 + dg)) * 64 + n];
    }
    __syncthreads();
    const int offA[7] = {0, 64, 127, 188, 245, 294, 327};
#pragma unroll
    for (int l = 1; l < 7; l++) {
        int cnt = 65 - (1 << l);
        int half = 1 << (l - 1);
        if (tid < 4 * cnt) {
            int dg = tid / cnt, p = tid - dg * cnt;
            lev[dg][offA[l] + p] = fmaxf(lev[dg][offA[l - 1] + p],
                                         lev[dg][offA[l - 1] + p + half]);
        }
        __syncthreads();
    }

    const float4* facv = (const float4*)(d_factor + (size_t)b * 4096);
    float4* gq0 = (float4*)out + (size_t)(b * BD + d0) * 1024;

    for (int idx = tid; idx < NNQ; idx += 256) {
        int q = g_ql.nq[idx];
        int4 t4 = ((const int4*)g_tbl.v)[q];
        float4 f4 = facv[q];
        int i  = q >> 4;
        int j0 = (q & 15) << 2;
        float fs[4] = {f4.x, f4.y, f4.z, f4.w};
        int   ts[4] = {t4.x, t4.y, t4.z, t4.w};

#pragma unroll
        for (int dg = 0; dg < 4; dg++) {
            const float* L = lev[dg];
            float xi = L[i];
            float bo[4], lc[4], co[4];
#pragma unroll
            for (int cc = 0; cc < 4; cc++) {
                int t = ts[cc];
                if (t < 0) { bo[cc] = 0.f; lc[cc] = 0.f; co[cc] = 0.f; }
                else {
                    int j = j0 + cc;
                    float xj = L[j];
                    float xk = L[(i + j) >> 1];
                    float f  = fs[cc];
                    bo[cc] = (xi + xj) * 0.5f * f;
                    lc[cc] = (xi + xj + 0.5f * xk) * (1.f / 2.5f) * f;
                    co[cc] = fmaxf(L[t & 1023], L[(t >> 10) & 1023]) * f;
                }
            }
            float4* p = gq0 + (size_t)dg * 1024 + q;
            __stcs(p,            make_float4(bo[0], bo[1], bo[2], bo[3]));
            __stcs(p + MAP4,     make_float4(lc[0], lc[1], lc[2], lc[3]));
            __stcs(p + 2 * MAP4, make_float4(co[0], co[1], co[2], co[3]));
        }
    }
}

// ---------------------------------------------------------------------------
extern "C" void kernel_launch(void* const* d_in, const int* in_sizes, int n_in,
                              void* d_out, int out_size) {
    const float* x   = (const float*)d_in[0];
    const float* w_c = (const float*)d_in[1];
    const float* b_c = (const float*)d_in[2];
    const float* w_v = (const float*)d_in[3];
    const float* b_v = (const float*)d_in[4];
    float* out = (float*)d_out;

    fused_kernel<<<768, 256>>>(x, w_v, w_c, out);
    attn_kernel<<<dim3(4, 16), 256>>>(b_v, b_c);
    main_kernel<<<dim3(128, 16), 256>>>(x, out);
}

// round 10
// speedup vs baseline: 1.9855x; 1.9855x over previous
#include <cuda_runtime.h>
#include <cstdint>

#define BN 64
#define BD 512
#define BB 16

// ---------------------------------------------------------------------------
// Compile-time structure table.
// Entry = i1 | (i2<<10) | 0x40000000 for masked (i,j): content = max(L[i1],L[i2])
// over a 7-level sparse max table; -1 for unmasked.
// ---------------------------------------------------------------------------
struct TblT { int v[4096]; };

constexpr int ilog2c(int v) { int l = 0; while ((1 << (l + 1)) <= v) l++; return l; }

constexpr int pack_entry_c(int a, int b) {
    int len = b - a;
    int l = ilog2c(len);
    const int off[7] = {0, 64, 127, 188, 245, 294, 327};
    int i1 = off[l] + a;
    int i2 = off[l] + b - (1 << l);
    return i1 | (i2 << 10) | 0x40000000;
}

constexpr TblT make_tbl() {
    TblT t{};
    for (int i = 0; i < 4096; i++) t.v[i] = -1;
    int lo[64] = {}, hi[64] = {};
    for (int p = 0; p < 64; p++) {
        lo[p] = p; hi[p] = p + 1;
        t.v[p * 64 + p] = pack_entry_c(p, p + 1);
    }
    int len = 64, stride = 1, offset = 0;
    const int counts[3] = {15, 8, 8};
    for (int ci = 0; ci < 3; ci++) {
        for (int tt = 0; tt < counts[ci]; tt++) {
            offset += stride;
            int k = (ci == 0 || tt > 0) ? 2 : 3;
            int s = (k == 2) ? 1 : 2;
            int nl = (len - k) / s + 1;
            for (int p = 0; p < nl; p++) {
                int a = lo[p * s];
                int b = hi[p * s + k - 1];
                lo[p] = a; hi[p] = b;
                int i = p * stride, j = i + offset;
                t.v[i * 64 + j] = pack_entry_c(a, b);
            }
            len = nl;
        }
        stride *= 2;
    }
    return t;
}

constexpr TblT HOST_TBL = make_tbl();
__device__ const TblT g_tbl = HOST_TBL;

// Scratch (static device globals — no allocations)
__device__ float d_part[2 * BB * 64 * 1024];  // K-split partial sums (no bias)
__device__ float d_factor[BB * 4096];         // 1 + softmax weights

// ---------------------------------------------------------------------------
// Kernel 1: K-split GEMM with 8x4 per-thread register tile (crossbar relief).
// partial[ks][b][n][o] = sum_{k in ks-half} x[b,k,n] * W[o,k]
// Tile: 128 o x 64 n, 256 threads, K=256 per split, double-buffered smem.
// Grid (8 o-tiles, 16 b, 2 ks).
// ---------------------------------------------------------------------------
__global__ __launch_bounds__(256) void gemm_kernel(
    const float* __restrict__ x, const float* __restrict__ w_v,
    const float* __restrict__ w_c)
{
    int b  = blockIdx.y;
    int o0 = blockIdx.x * 128;
    int ks = blockIdx.z;
    const float* W = (o0 < 512) ? (w_v + (size_t)o0 * 512)
                                : (w_c + (size_t)(o0 - 512) * 512);
    W += ks * 256;
    const float* xb = x + (size_t)b * BD * BN + (size_t)ks * 256 * 64;

    __shared__ float As[2][16][64];    // [kk][n]
    __shared__ float Ws[2][16][132];   // [kk][o], padded row

    int tid = threadIdx.x;
    int tx = tid & 15;        // n-group: 4 n per thread
    int ty = tid >> 4;        // o-group: 8 o per thread
    int ld_o    = tid & 127;  // Ws loader: one o row
    int ld_half = tid >> 7;   // k-halves 0..7 / 8..15

    float acc[8][4];
#pragma unroll
    for (int r = 0; r < 8; r++)
#pragma unroll
        for (int c = 0; c < 4; c++) acc[r][c] = 0.f;

    // prologue: tile 0 -> slot 0
    {
        int kk = tid >> 4, n4 = tid & 15;
        *(float4*)&As[0][kk][n4 * 4] = *(const float4*)(xb + (size_t)kk * 64 + n4 * 4);
        float4 v0 = *(const float4*)(W + (size_t)ld_o * 512 + ld_half * 8);
        float4 v1 = *(const float4*)(W + (size_t)ld_o * 512 + ld_half * 8 + 4);
        Ws[0][ld_half * 8 + 0][ld_o] = v0.x; Ws[0][ld_half * 8 + 1][ld_o] = v0.y;
        Ws[0][ld_half * 8 + 2][ld_o] = v0.z; Ws[0][ld_half * 8 + 3][ld_o] = v0.w;
        Ws[0][ld_half * 8 + 4][ld_o] = v1.x; Ws[0][ld_half * 8 + 5][ld_o] = v1.y;
        Ws[0][ld_half * 8 + 6][ld_o] = v1.z; Ws[0][ld_half * 8 + 7][ld_o] = v1.w;
    }
    __syncthreads();

    for (int t = 0; t < 16; t++) {
        int s = t & 1, ns = s ^ 1;
        if (t < 15) {
            int kb = (t + 1) * 16;
            int kk = tid >> 4, n4 = tid & 15;
            *(float4*)&As[ns][kk][n4 * 4] =
                *(const float4*)(xb + (size_t)(kb + kk) * 64 + n4 * 4);
            float4 v0 = *(const float4*)(W + (size_t)ld_o * 512 + kb + ld_half * 8);
            float4 v1 = *(const float4*)(W + (size_t)ld_o * 512 + kb + ld_half * 8 + 4);
            Ws[ns][ld_half * 8 + 0][ld_o] = v0.x; Ws[ns][ld_half * 8 + 1][ld_o] = v0.y;
            Ws[ns][ld_half * 8 + 2][ld_o] = v0.z; Ws[ns][ld_half * 8 + 3][ld_o] = v0.w;
            Ws[ns][ld_half * 8 + 4][ld_o] = v1.x; Ws[ns][ld_half * 8 + 5][ld_o] = v1.y;
            Ws[ns][ld_half * 8 + 6][ld_o] = v1.z; Ws[ns][ld_half * 8 + 7][ld_o] = v1.w;
        }
#pragma unroll
        for (int kk = 0; kk < 16; kk++) {
            float4 n4 = *(const float4*)&As[s][kk][tx * 4];
            float4 o40 = *(const float4*)&Ws[s][kk][ty * 8];
            float4 o41 = *(const float4*)&Ws[s][kk][ty * 8 + 4];
            float nv[4] = {n4.x, n4.y, n4.z, n4.w};
            float ov[8] = {o40.x, o40.y, o40.z, o40.w, o41.x, o41.y, o41.z, o41.w};
#pragma unroll
            for (int r = 0; r < 8; r++)
#pragma unroll
                for (int c = 0; c < 4; c++)
                    acc[r][c] += ov[r] * nv[c];
        }
        __syncthreads();
    }

    // Epilogue: partials (no bias) -> d_part[ks][b][n][o], float4 along o.
    float* dst = d_part + ((size_t)ks * BB + b) * 65536;
#pragma unroll
    for (int c = 0; c < 4; c++) {
        int n = tx * 4 + c;
        float4 lo = make_float4(acc[0][c], acc[1][c], acc[2][c], acc[3][c]);
        float4 hi = make_float4(acc[4][c], acc[5][c], acc[6][c], acc[7][c]);
        *(float4*)&dst[(size_t)n * 1024 + o0 + ty * 8]     = lo;
        *(float4*)&dst[(size_t)n * 1024 + o0 + ty * 8 + 4] = hi;
    }
}

// ---------------------------------------------------------------------------
// Kernel 2: combine partials + bias on the fly; m2m = m_k @ m_q^T / 8,
// row softmax, factor = 1 + w.
// ---------------------------------------------------------------------------
__global__ __launch_bounds__(256) void attn_kernel(
    const float* __restrict__ b_v, const float* __restrict__ b_c)
{
    int b = blockIdx.y;
    int n0 = blockIdx.x * 16;
    __shared__ float Sk[16][33];
    __shared__ float Sq[32][68];
    __shared__ float sm[16][68];
    __shared__ float red[16];
    int tid = threadIdx.x;
    int tr = tid >> 4, tc = tid & 15;
    float acc[4] = {0, 0, 0, 0};
    const float* P0 = d_part + (size_t)b * 65536;
    const float* P1 = d_part + (size_t)(BB + b) * 65536;

    for (int kt = 0; kt < 512; kt += 32) {
#pragma unroll
        for (int it = 0; it < 2; it++) {
            int u = tid + it * 256;
            int r = u >> 5, kk = u & 31;
            size_t off = (size_t)(n0 + r) * 1024 + kt + kk;
            Sk[r][kk] = P0[off] + P1[off] + b_v[kt + kk];
        }
#pragma unroll
        for (int it = 0; it < 2; it++) {
            int u = tid + it * 256;
            int m = u >> 3, c4 = u & 7;
            size_t off = (size_t)m * 1024 + 512 + kt + c4 * 4;
            float4 v0 = *(const float4*)(P0 + off);
            float4 v1 = *(const float4*)(P1 + off);
            float4 vb = *(const float4*)(b_c + kt + c4 * 4);
            Sq[c4 * 4 + 0][m] = v0.x + v1.x + vb.x;
            Sq[c4 * 4 + 1][m] = v0.y + v1.y + vb.y;
            Sq[c4 * 4 + 2][m] = v0.z + v1.z + vb.z;
            Sq[c4 * 4 + 3][m] = v0.w + v1.w + vb.w;
        }
        __syncthreads();
#pragma unroll
        for (int kk = 0; kk < 32; kk++) {
            float a = Sk[tr][kk];
            float4 b4 = *(const float4*)&Sq[kk][tc * 4];
            acc[0] += a * b4.x; acc[1] += a * b4.y;
            acc[2] += a * b4.z; acc[3] += a * b4.w;
        }
        __syncthreads();
    }
#pragma unroll
    for (int c = 0; c < 4; c++) sm[tr][tc * 4 + c] = acc[c] * 0.125f;
    __syncthreads();
    if (tid < 16) {
        float mx = -1e30f;
        for (int m = 0; m < 64; m++) mx = fmaxf(mx, sm[tid][m]);
        red[tid] = mx;
    }
    __syncthreads();
    float mx = red[tr];
    float e[4];
#pragma unroll
    for (int c = 0; c < 4; c++) {
        e[c] = __expf(sm[tr][tc * 4 + c] - mx);
        sm[tr][tc * 4 + c] = e[c];
    }
    __syncthreads();
    if (tid < 16) {
        float s = 0.f;
        for (int m = 0; m < 64; m++) s += sm[tid][m];
        red[tid] = 1.f / s;
    }
    __syncthreads();
    float inv = red[tr];
#pragma unroll
    for (int c = 0; c < 4; c++)
        d_factor[(size_t)b * 4096 + (size_t)(n0 + tr) * 64 + tc * 4 + c] = 1.f + e[c] * inv;
}

// ---------------------------------------------------------------------------
// Kernel 3 (R4-proven): one block per (b, d). Row processed in 4 chunks of
// 1024 elements, double-buffered smem; each chunk drains via three 4 KB
// cp.async.bulk stores in one bulk group. Dynamic smem: 24 KB.
// ---------------------------------------------------------------------------
#define SMEM_MAIN_BYTES (2 * 3 * 1024 * 4)

__global__ __launch_bounds__(256) void main_kernel(
    const float* __restrict__ x, float* __restrict__ out)
{
    __shared__ float lev[352];
    extern __shared__ float smb[];   // [2][3][1024]

    int b = blockIdx.y;
    int d = blockIdx.x;
    int tid = threadIdx.x;

    if (tid < 64) lev[tid] = x[((size_t)(b * BD + d)) * 64 + tid];
    __syncthreads();
    const int offA[7] = {0, 64, 127, 188, 245, 294, 327};
#pragma unroll
    for (int l = 1; l < 7; l++) {
        int cnt = 65 - (1 << l);
        int half = 1 << (l - 1);
        if (tid < cnt)
            lev[offA[l] + tid] = fmaxf(lev[offA[l - 1] + tid],
                                       lev[offA[l - 1] + tid + half]);
        __syncthreads();
    }

    const size_t mapsz = (size_t)BB * BD * 4096;
    const int4*   tblv = (const int4*)g_tbl.v;
    const float4* facv = (const float4*)(d_factor + (size_t)b * 4096);
    float* maskp = out + 3 * mapsz + (size_t)b * 4096;
    float* gBase = out + ((size_t)(b * BD + d)) * 4096;

#pragma unroll
    for (int c = 0; c < 4; c++) {
        float* buf = smb + (c & 1) * 3072;
        if (c >= 2) {
            if (tid == 0)
                asm volatile("cp.async.bulk.wait_group.read 1;" ::: "memory");
            __syncthreads();
        }

        int q = c * 256 + tid;
        int4 t4 = tblv[q];
        int i  = q >> 4;
        int j0 = (q & 15) << 2;
        float4* pB = (float4*)buf + tid;
        float4* pL = (float4*)buf + 256 + tid;
        float4* pC = (float4*)buf + 512 + tid;

        if ((t4.x & t4.y & t4.z & t4.w) < 0) {
            float4 z = make_float4(0.f, 0.f, 0.f, 0.f);
            *pB = z; *pL = z; *pC = z;
            if (d == 0) __stcs((float4*)maskp + q, z);
        } else {
            float4 f4 = facv[q];
            float fs[4] = {f4.x, f4.y, f4.z, f4.w};
            int   ts[4] = {t4.x, t4.y, t4.z, t4.w};
            float xi = lev[i];
            float bo[4], lc[4], co[4], mk[4];
#pragma unroll
            for (int cc = 0; cc < 4; cc++) {
                int t = ts[cc];
                if (t < 0) { bo[cc] = 0.f; lc[cc] = 0.f; co[cc] = 0.f; mk[cc] = 0.f; }
                else {
                    int j = j0 + cc;
                    float xj = lev[j];
                    float xk = lev[(i + j) >> 1];
                    float f  = fs[cc];
                    bo[cc] = (xi + xj) * 0.5f * f;
                    lc[cc] = (xi + xj + 0.5f * xk) * (1.f / 2.5f) * f;
                    co[cc] = fmaxf(lev[t & 1023], lev[(t >> 10) & 1023]) * f;
                    mk[cc] = 1.f;
                }
            }
            *pB = make_float4(bo[0], bo[1], bo[2], bo[3]);
            *pL = make_float4(lc[0], lc[1], lc[2], lc[3]);
            *pC = make_float4(co[0], co[1], co[2], co[3]);
            if (d == 0) __stcs((float4*)maskp + q,
                               make_float4(mk[0], mk[1], mk[2], mk[3]));
        }
        __syncthreads();

        if (tid == 0) {
            uint32_t s0;
            asm("{ .reg .u64 t; cvta.to.shared.u64 t, %1; cvt.u32.u64 %0, t; }"
                : "=r"(s0) : "l"(buf));
            asm volatile("fence.proxy.async.shared::cta;" ::: "memory");
            asm volatile("cp.async.bulk.global.shared::cta.bulk_group [%0], [%1], %2;"
                         :: "l"(gBase + c * 1024), "r"(s0), "r"(4096) : "memory");
            asm volatile("cp.async.bulk.global.shared::cta.bulk_group [%0], [%1], %2;"
                         :: "l"(gBase + mapsz + c * 1024), "r"(s0 + 4096), "r"(4096) : "memory");
            asm volatile("cp.async.bulk.global.shared::cta.bulk_group [%0], [%1], %2;"
                         :: "l"(gBase + 2 * mapsz + c * 1024), "r"(s0 + 8192), "r"(4096) : "memory");
            asm volatile("cp.async.bulk.commit_group;" ::: "memory");
        }
    }

    if (tid == 0)
        asm volatile("cp.async.bulk.wait_group.read 0;" ::: "memory");
}

// ---------------------------------------------------------------------------
extern "C" void kernel_launch(void* const* d_in, const int* in_sizes, int n_in,
                              void* d_out, int out_size) {
    const float* x   = (const float*)d_in[0];
    const float* w_c = (const float*)d_in[1];
    const float* b_c = (const float*)d_in[2];
    const float* w_v = (const float*)d_in[3];
    const float* b_v = (const float*)d_in[4];
    float* out = (float*)d_out;

    gemm_kernel<<<dim3(8, 16, 2), 256>>>(x, w_v, w_c);
    attn_kernel<<<dim3(4, 16), 256>>>(b_v, b_c);
    main_kernel<<<dim3(512, 16), 256, SMEM_MAIN_BYTES>>>(x, out);
}